// round 5
// baseline (speedup 1.0000x reference)
#include <cuda_runtime.h>

// BinsChamferLoss: exact 1-D bidirectional chamfer.
// bins [L=4, N=4, 257] f32, depth [N=4, 240, 320] f32 -> scalar f32.
//
// k_prep : centers, bitonic sort (16 lists of 256), 2048-bucket LUT per (l,n)
//          built by one binary search + monotone walk; entry {cl,cm,cr,j0|dj<<16}.
//          For pure buckets (dj=0) cm is set to cr so the branchless fast path
//          selects {j0, cl, cr} (R4 bug: cm=+inf leaked inf into cham_y).
// k_main : per valid pixel: 2 global REDG into per-batch fixed-bucket y min/max
//          (shared across scales). Per scale: one 16B LUT load gives segment j
//          + neighbor centers branchlessly (dj<=1); cham_y in registers; only
//          mixed buckets (dj>0) emit per-(scale,segment) REDG.
// k_final: 16 blocks (one per l,n). Pure buckets lie entirely inside one
//          segment -> warp-segmented shfl max/min merge of bucket aggregates
//          into the segment arrays (exact). Warp-parallel prefix-max/suffix-min
//          over 257 segments -> cham_x; atomicAdd contribution to out.

#define LSC 4
#define NB  4
#define P   256
#define P1  257
#define M   76800
#define LNN 16
#define NBY 2048
#define BPB 75
#define GRID (NB*BPB)     // 300
#define PPB 1024          // pixels per block (256 thr x float4)
#define INFB 0x7F800000u

__device__ float    g_sortedC[LNN][P];
__device__ float4   g_lut[NB * NBY * LSC];   // [(n*NBY+b)*4 + l]
__device__ unsigned g_segMax[LNN][P1];       // mixed-bucket pixels only
__device__ unsigned g_segMin[LNN][P1];
__device__ unsigned g_bMax[NB][NBY];         // all pixels, per fixed bucket
__device__ unsigned g_bMin[NB][NBY];
__device__ float    g_sumY[LNN];
__device__ unsigned g_cnt[NB];

__global__ void k_prep(const float* __restrict__ bins, float* __restrict__ out)
{
    const int ln = blockIdx.x;
    const int l = ln >> 2, n = ln & 3;
    const int t = threadIdx.x;
    __shared__ float s[P];

    const float* e = bins + ln * P1;
    float v = 0.5f * (e[t] + e[t + 1]);

    // re-init accumulators (graph replay safe)
    for (int i = t; i < P1; i += P) { g_segMax[ln][i] = 0u; g_segMin[ln][i] = INFB; }
    if (ln < NB)
        for (int i = t; i < NBY; i += P) { g_bMax[ln][i] = 0u; g_bMin[ln][i] = INFB; }
    if (t == 0) {
        g_sumY[ln] = 0.f;
        if (ln < NB) g_cnt[ln] = 0u;
        if (ln == 0) out[0] = 0.f;
    }

    // bitonic sort: shfl for j<32, smem for j>=32
    #pragma unroll
    for (int k = 2; k <= P; k <<= 1) {
        #pragma unroll
        for (int j = k >> 1; j > 0; j >>= 1) {
            bool asc   = ((t & k) == 0);
            bool lower = ((t & j) == 0);
            float pv;
            if (j < 32) {
                pv = __shfl_xor_sync(0xffffffffu, v, j);
            } else {
                __syncthreads();
                s[t] = v;
                __syncthreads();
                pv = s[t ^ j];
            }
            v = (lower == asc) ? fminf(v, pv) : fmaxf(v, pv);
        }
    }
    __syncthreads();
    s[t] = v;
    g_sortedC[ln][t] = v;
    __syncthreads();

    // LUT build: thread t owns buckets [8t, 8t+8); one search, then walk.
    // strict counts: j = #centers < boundary  (boundaries exact: pow2 scale)
    float lo0 = (float)(8 * t) * (1.f / (float)NBY);
    int j = 0;
    #pragma unroll
    for (int st = 256; st > 0; st >>= 1)
        if (j + st <= P && s[j + st - 1] < lo0) j += st;

    #pragma unroll
    for (int q = 0; q < 8; q++) {
        int b = 8 * t + q;
        float hi = (float)(b + 1) * (1.f / (float)NBY);
        int j0 = j;
        while (j < P && s[j] < hi) j++;         // centers in [lo(b), hi(b))
        int dj = j - j0;
        float4 ent;
        ent.x = (j0 > 0) ? s[j0 - 1] : -1e18f;  // cl: last center < lo
        ent.z = (j < P) ? s[j] : 1e18f;         // cr: first center >= hi
        // cm: first center in bucket; for pure buckets use cr so the fast
        // path's (y >= cm) is always false and selects {j0, cl, cr}.
        ent.y = dj ? s[j0] : ent.z;
        ent.w = __uint_as_float((unsigned)j0 | ((unsigned)dj << 16));
        g_lut[(n * NBY + b) * LSC + l] = ent;
    }
}

__global__ void __launch_bounds__(256) k_main(const float* __restrict__ depth)
{
    const int n  = blockIdx.x / BPB;
    const int cb = blockIdx.x % BPB;
    const int t  = threadIdx.x;
    const int lane = t & 31;

    float4 yv = __ldg((const float4*)(depth + n * M + cb * PPB) + t);
    const float4* lutN = &g_lut[n * NBY * LSC];

    float sums[LSC] = {0.f, 0.f, 0.f, 0.f};
    unsigned cnt = 0;
    float ys[4] = {yv.x, yv.y, yv.z, yv.w};

    #pragma unroll
    for (int p = 0; p < 4; p++) {
        float y = ys[p];
        if (y >= 0.001f) {
            cnt++;
            unsigned uy = __float_as_uint(y);
            int b = (int)__fmul_rd(y, (float)NBY);      // exact floor, y in [0,1)
            atomicMax(&g_bMax[n][b], uy);
            atomicMin(&g_bMin[n][b], uy);
            const float4* le = lutN + b * LSC;
            #pragma unroll
            for (int l = 0; l < LSC; l++) {
                float4 ent = __ldg(le + l);
                unsigned meta = __float_as_uint(ent.w);
                int j0 = (int)(meta & 0xffffu);
                int dj = (int)(meta >> 16);
                int j; float cL, cR;
                if (dj < 2) {                            // pure (cm=cr) or 1 center
                    bool up = (y >= ent.y);
                    j  = j0 + (up ? 1 : 0);
                    cL = up ? ent.y : ent.x;
                    cR = up ? ent.z : ent.y;
                } else {                                 // >=2 centers in bucket (rare)
                    const float* cc = g_sortedC[l * NB + n];
                    int j1 = j0 + dj;
                    j = j0; cL = ent.x;
                    while (j < j1) {
                        float cv = __ldg(cc + j);
                        if (cv <= y) { cL = cv; j++; } else break;
                    }
                    cR = (j < j1) ? __ldg(cc + j) : ent.z;
                }
                float dl = y - cL, dr = cR - y;
                sums[l] += fminf(dl * dl, dr * dr);
                if (dj) {                                // mixed bucket -> direct segment REDG
                    atomicMax(&g_segMax[l * NB + n][j], uy);
                    atomicMin(&g_segMin[l * NB + n][j], uy);
                }
            }
        }
    }

    // cham_y partial sums -> global (one atomic per warp per accumulator)
    #pragma unroll
    for (int off = 16; off; off >>= 1) {
        #pragma unroll
        for (int l = 0; l < LSC; l++)
            sums[l] += __shfl_down_sync(0xffffffffu, sums[l], off);
        cnt += __shfl_down_sync(0xffffffffu, cnt, off);
    }
    if (lane == 0) {
        #pragma unroll
        for (int l = 0; l < LSC; l++)
            atomicAdd(&g_sumY[l * NB + n], sums[l]);
        atomicAdd(&g_cnt[n], cnt);
    }
}

__global__ void __launch_bounds__(256) k_final(float* __restrict__ out)
{
    __shared__ unsigned uMax[P1], uMin[P1];
    const int ln = blockIdx.x;
    const int l = ln >> 2, n = ln & 3;
    const int t = threadIdx.x, w = t >> 5, lane = t & 31;

    for (int i = t; i < P1; i += 256) { uMax[i] = g_segMax[ln][i]; uMin[i] = g_segMin[ln][i]; }
    __syncthreads();

    // merge pure buckets into their (single) segment; warp w owns buckets [256w, 256w+256)
    #pragma unroll
    for (int k = 0; k < 8; k++) {
        int b = w * 256 + k * 32 + lane;
        unsigned bm = g_bMax[n][b];
        unsigned bn = g_bMin[n][b];
        float4 ent = __ldg(&g_lut[(n * NBY + b) * LSC + l]);
        unsigned meta = __float_as_uint(ent.w);
        int j = (int)(meta & 0xffffu);
        bool pure = ((meta >> 16) == 0);
        unsigned um = pure ? bm : 0u;       // identity if mixed or empty
        unsigned un = pure ? bn : INFB;
        // warp-segmented inclusive max/min keyed by j (monotone across lanes)
        #pragma unroll
        for (int off = 1; off < 32; off <<= 1) {
            unsigned om = __shfl_up_sync(0xffffffffu, um, off);
            unsigned on = __shfl_up_sync(0xffffffffu, un, off);
            int      oj = __shfl_up_sync(0xffffffffu, j,  off);
            if (lane >= off && oj == j) { um = max(um, om); un = min(un, on); }
        }
        int jn = __shfl_down_sync(0xffffffffu, j, 1);
        bool tail = (lane == 31) || (jn != j);
        if (tail) {
            if (um)         atomicMax(&uMax[j], um);
            if (un != INFB) atomicMin(&uMin[j], un);
        }
    }
    __syncthreads();

    if (w == 0) {
        // warp-parallel prefix-max / suffix-min over 257 segments; lane owns 9
        const float NEG = -1e30f;
        const float INF = __int_as_float(0x7F800000);
        int base = lane * 9;
        float emx[9], emn[9];
        #pragma unroll
        for (int q = 0; q < 9; q++) {
            int i = base + q;
            if (i < P1) {
                unsigned u = uMax[i];
                emx[q] = u ? __uint_as_float(u) : NEG;
                emn[q] = __uint_as_float(uMin[i]);
            } else { emx[q] = NEG; emn[q] = INF; }
        }
        float pre[9], run = NEG;
        #pragma unroll
        for (int q = 0; q < 9; q++) { run = fmaxf(run, emx[q]); pre[q] = run; }
        float vmax = run;
        #pragma unroll
        for (int off = 1; off < 32; off <<= 1) {
            float o = __shfl_up_sync(0xffffffffu, vmax, off);
            if (lane >= off) vmax = fmaxf(vmax, o);
        }
        float exL = __shfl_up_sync(0xffffffffu, vmax, 1);
        if (lane == 0) exL = NEG;

        float suf[10], runm = INF;
        #pragma unroll
        for (int q = 8; q >= 0; q--) { runm = fminf(runm, emn[q]); suf[q] = runm; }
        float vmin = runm;
        #pragma unroll
        for (int off = 1; off < 32; off <<= 1) {
            float o = __shfl_down_sync(0xffffffffu, vmin, off);
            if (lane < 32 - off) vmin = fminf(vmin, o);
        }
        float exR = __shfl_down_sync(0xffffffffu, vmin, 1);
        if (lane == 31) exR = INF;
        suf[9] = INF;

        float s = 0.f;
        #pragma unroll
        for (int q = 0; q < 9; q++) {
            int i = base + q;
            if (i < P) {
                float c  = __ldg(&g_sortedC[ln][i]);
                float pm = fmaxf(pre[q], exL);
                float sm = fminf(suf[q + 1], exR);
                float dl = c - pm;
                float dr = sm - c;
                s += fminf(dl * dl, dr * dr);
            }
        }
        #pragma unroll
        for (int off = 16; off; off >>= 1)
            s += __shfl_down_sync(0xffffffffu, s, off);
        if (lane == 0) {
            float contrib = s * (1.f / P) + g_sumY[ln] / (float)g_cnt[n];
            atomicAdd(out, contrib * 0.25f);    // mean over batch, summed over scales
        }
    }
}

extern "C" void kernel_launch(void* const* d_in, const int* in_sizes, int n_in,
                              void* d_out, int out_size)
{
    const float* bins  = (const float*)d_in[0];
    const float* depth = (const float*)d_in[1];
    float* out = (float*)d_out;

    k_prep <<<LNN, P>>>(bins, out);
    k_main <<<GRID, 256>>>(depth);
    k_final<<<LNN, 256>>>(out);
}

// round 6
// speedup vs baseline: 1.0616x; 1.0616x over previous
#include <cuda_runtime.h>

// BinsChamferLoss: 1-D bidirectional chamfer.
// bins [L=4, N=4, 257] f32, depth [N=4, 240, 320] f32 -> scalar f32.
//
// cham_y (dominant term, ~3e-5): exact via a 1024-bucket candidate LUT per
//   (l,n): candidates {nearest center below bucket, in-bucket min, in-bucket
//   max, nearest center above bucket}; min-of-4 squared distances. Exact for
//   buckets with <=2 centers; >=3-center buckets (P~2.6e-3) err <~3e-5 rel.
// cham_x (true value ~1e-10, tolerance 1e-3): approximated from per-batch
//   8192-bucket valid-y min/max extremes; per center, nearest known y =
//   extremes of first nonempty bucket scanning down/up. Abs err <~1.2e-9.
//
// k_prep : centers, smem bucket scatter (no sort!), Hillis-Steele prefix-max /
//          suffix-min scans over 1024 buckets, write negated-candidate LUT.
//          Zeroes all accumulators (graph-replay safe).
// k_main : 300 blocks x 256 thr x 4 pixels. Per valid pixel: 2 global REDG
//          (y-extreme buckets) + 4 x (LDG.128 + f32x2 math). Warp-reduced
//          cham_y sums. Last 4 ticket blocks spin for completion then
//          finalize one batch each and atomicAdd into out.

#define LSC 4
#define NB  4
#define P   256
#define P1  257
#define M   76800
#define LNN 16
#define NCB 1024          // center-LUT buckets
#define NYB 8192          // y-extreme buckets
#define BPB 75
#define GRID (NB*BPB)     // 300
#define PPB 1024
#define INFB 0x7F800000u

#define PACK_F32X2(out, lo, hi) \
    asm("mov.b64 %0, {%1, %2};" : "=l"(out) : "f"(lo), "f"(hi))
#define ADD_F32X2(out, a, b) \
    asm("add.rn.f32x2 %0, %1, %2;" : "=l"(out) : "l"(a), "l"(b))
#define MUL_F32X2(out, a, b) \
    asm("mul.rn.f32x2 %0, %1, %2;" : "=l"(out) : "l"(a), "l"(b))
#define UNPACK_F32X2(lo, hi, in) \
    asm("mov.b64 {%0, %1}, %2;" : "=f"(lo), "=f"(hi) : "l"(in))

__device__ float    g_centers[LNN][P];
__device__ float4   g_lutF[NB * NCB * LSC];   // [(n*NCB+b)*4 + l] = {-cL,-cA,-cB,-cR}
__device__ unsigned g_yMax[NB][NYB];          // valid-y max per bucket (bits; 0 = empty)
__device__ unsigned g_yMin[NB][NYB];          // valid-y min per bucket (bits; +inf = empty)
__device__ float    g_sumY[LNN];
__device__ unsigned g_cnt[NB];
__device__ unsigned g_done;

__global__ void k_prep(const float* __restrict__ bins, float* __restrict__ out)
{
    const int ln = blockIdx.x;
    const int l = ln >> 2, n = ln & 3;
    const int t = threadIdx.x;

    __shared__ unsigned sMaxU[NCB], sMinU[NCB];
    __shared__ float    bufA[NCB], bufB[NCB], sPref[NCB];

    // zero y-extreme buckets: block ln owns 1/16 of each array
    {
        unsigned* ym = &g_yMax[0][0];
        unsigned* yn = &g_yMin[0][0];
        const int slice = NB * NYB / LNN;            // 2048
        for (int i = t; i < slice; i += P) {
            ym[ln * slice + i] = 0u;
            yn[ln * slice + i] = INFB;
        }
    }
    if (t == 0) {
        g_sumY[ln] = 0.f;
        if (ln < NB) g_cnt[ln] = 0u;
        if (ln == 0) { g_done = 0u; out[0] = 0.f; }
    }

    // centers + smem bucket scatter
    for (int i = t; i < NCB; i += P) { sMaxU[i] = 0u; sMinU[i] = INFB; }
    __syncthreads();

    const float* e = bins + ln * P1;
    float c = 0.5f * (e[t] + e[t + 1]);
    g_centers[ln][t] = c;
    int bc = (int)__fmul_rd(c, (float)NCB);          // c in [0,1)
    unsigned cu = __float_as_uint(c);                // nonneg: uint order == float order
    atomicMax(&sMaxU[bc], cu);
    atomicMin(&sMinU[bc], cu);
    __syncthreads();

    // inclusive prefix-max of per-bucket max (Hillis-Steele, ping-pong)
    for (int i = t; i < NCB; i += P)
        bufA[i] = sMaxU[i] ? __uint_as_float(sMaxU[i]) : -1e18f;
    __syncthreads();
    {
        float *src = bufA, *dst = bufB;
        for (int d = 1; d < NCB; d <<= 1) {
            for (int i = t; i < NCB; i += P) {
                float v = src[i];
                if (i >= d) v = fmaxf(v, src[i - d]);
                dst[i] = v;
            }
            __syncthreads();
            float* tmp = src; src = dst; dst = tmp;
        }
        for (int i = t; i < NCB; i += P) sPref[i] = src[i];
        __syncthreads();
    }
    // inclusive suffix-min of per-bucket min
    for (int i = t; i < NCB; i += P)
        bufA[i] = (sMinU[i] != INFB) ? __uint_as_float(sMinU[i]) : 1e18f;
    __syncthreads();
    float* ssuf;
    {
        float *src = bufA, *dst = bufB;
        for (int d = 1; d < NCB; d <<= 1) {
            for (int i = t; i < NCB; i += P) {
                float v = src[i];
                if (i + d < NCB) v = fminf(v, src[i + d]);
                dst[i] = v;
            }
            __syncthreads();
            float* tmp = src; src = dst; dst = tmp;
        }
        ssuf = src;
    }

    // write LUT entries (negated candidates; sentinels -> +/-1e18, squared stays finite/huge)
    for (int i = t; i < NCB; i += P) {
        float cL = (i > 0)       ? sPref[i - 1] : -1e18f;
        float cR = (i < NCB - 1) ? ssuf[i + 1]  :  1e18f;
        unsigned mu = sMaxU[i], nu = sMinU[i];
        float stcA = (nu != INFB) ? -__uint_as_float(nu) : 1e18f;
        float stcB = (mu != 0u)   ? -__uint_as_float(mu) : 1e18f;
        g_lutF[(n * NCB + i) * LSC + l] = make_float4(-cL, stcA, stcB, -cR);
    }
}

__global__ void __launch_bounds__(256) k_main(const float* __restrict__ depth,
                                              float* __restrict__ out)
{
    __shared__ int   sTicket;
    __shared__ float sRed[8][LSC];

    const int n  = blockIdx.x / BPB;
    const int cb = blockIdx.x % BPB;
    const int t  = threadIdx.x;
    const int lane = t & 31, w = t >> 5;

    float4 yv = __ldg((const float4*)(depth + n * M + cb * PPB) + t);
    const float4* lutN = g_lutF + n * NCB * LSC;

    float sums[LSC] = {0.f, 0.f, 0.f, 0.f};
    unsigned cnt = 0;
    float ys[4] = {yv.x, yv.y, yv.z, yv.w};

    #pragma unroll
    for (int p = 0; p < 4; p++) {
        float y = ys[p];
        if (y >= 0.001f) {
            cnt++;
            unsigned uy = __float_as_uint(y);
            int b13 = (int)__fmul_rd(y, (float)NYB);    // exact floor, y in [0,1)
            atomicMax(&g_yMax[n][b13], uy);
            atomicMin(&g_yMin[n][b13], uy);
            int b10 = b13 >> 3;                         // 8192 -> 1024
            unsigned long long y2;
            PACK_F32X2(y2, y, y);
            const ulonglong2* le = (const ulonglong2*)(lutN + b10 * LSC);
            #pragma unroll
            for (int l = 0; l < LSC; l++) {
                ulonglong2 ent = __ldg(le + l);
                unsigned long long d0, d1, s0, s1;
                ADD_F32X2(d0, y2, ent.x);
                ADD_F32X2(d1, y2, ent.y);
                MUL_F32X2(s0, d0, d0);
                MUL_F32X2(s1, d1, d1);
                float a, b, cc, d;
                UNPACK_F32X2(a, b, s0);
                UNPACK_F32X2(cc, d, s1);
                sums[l] += fminf(fminf(a, b), fminf(cc, d));
            }
        }
    }

    // cham_y partial sums -> global (one atomic per warp per accumulator)
    #pragma unroll
    for (int off = 16; off; off >>= 1) {
        #pragma unroll
        for (int l = 0; l < LSC; l++)
            sums[l] += __shfl_down_sync(0xffffffffu, sums[l], off);
        cnt += __shfl_down_sync(0xffffffffu, cnt, off);
    }
    if (lane == 0) {
        #pragma unroll
        for (int l = 0; l < LSC; l++)
            atomicAdd(&g_sumY[l * NB + n], sums[l]);
        atomicAdd(&g_cnt[n], cnt);
    }

    // completion ticket
    __threadfence();
    __syncthreads();
    if (t == 0) sTicket = (int)atomicAdd(&g_done, 1u);
    __syncthreads();
    if (sTicket < GRID - NB) return;
    const int nf = sTicket - (GRID - NB);     // this block finalizes batch nf

    if (t == 0) {
        while (atomicAdd(&g_done, 0u) < GRID) __nanosleep(64);
    }
    __syncthreads();
    __threadfence();

    // cham_x approx: thread t handles center index t for each scale
    float part[LSC];
    #pragma unroll
    for (int l = 0; l < LSC; l++) {
        float c = g_centers[l * NB + nf][t];
        int b = (int)__fmul_rd(c, (float)NYB);
        float dL2 = 1e12f, dU2 = 1e12f;
        for (int i = b; i >= 0; --i) {                // ~1 step (buckets dense)
            unsigned u = g_yMax[nf][i];
            if (u) { float d = c - __uint_as_float(u); dL2 = d * d; break; }
        }
        for (int i = b; i < NYB; ++i) {
            unsigned u = g_yMin[nf][i];
            if (u != INFB) { float d = __uint_as_float(u) - c; dU2 = d * d; break; }
        }
        part[l] = fminf(dL2, dU2);
    }
    #pragma unroll
    for (int l = 0; l < LSC; l++) {
        float s = part[l];
        #pragma unroll
        for (int off = 16; off; off >>= 1)
            s += __shfl_down_sync(0xffffffffu, s, off);
        if (lane == 0) sRed[w][l] = s;
    }
    __syncthreads();
    if (t == 0) {
        float contrib = 0.f;
        float invCnt = 1.f / (float)g_cnt[nf];
        #pragma unroll
        for (int l = 0; l < LSC; l++) {
            float cx = 0.f;
            #pragma unroll
            for (int ww = 0; ww < 8; ww++) cx += sRed[ww][l];
            contrib += cx * (1.f / P) + g_sumY[l * NB + nf] * invCnt;
        }
        atomicAdd(out, contrib * 0.25f);     // mean over batch, summed over scales
    }
}

extern "C" void kernel_launch(void* const* d_in, const int* in_sizes, int n_in,
                              void* d_out, int out_size)
{
    const float* bins  = (const float*)d_in[0];
    const float* depth = (const float*)d_in[1];
    float* out = (float*)d_out;

    k_prep<<<LNN, P>>>(bins, out);
    k_main<<<GRID, 256>>>(depth, out);
}